// round 17
// baseline (speedup 1.0000x reference)
#include <cuda_runtime.h>
#include <cstdint>

// EfficientGCN preprocess on GB300 — smem-tiled compute + TMA bulk stores.
// x: (N=128, C=3, T=300, V=25, M=2) fp32, conn: int32[25]
// out: (N, 3, 6, T, V, M) fp32
//
// Block = (n, 10-row t-tile). Stage input tile (7.2KB), compute per-(t,v)
// into a 36KB smem output tile (STS only, no per-thread STG), then ONE thread
// issues 18x cp.async.bulk (2000B contiguous slab segments) via the TMA
// engine — the 138MB write stream leaves the per-thread L1tex path entirely.

#define N_ 128
#define C_ 3
#define T_ 300
#define V_ 25
#define RPT 10            // t-rows computed per tile
#define TILE_ROWS 12      // RPT + 2 halo
#define TILES_PER_N 30    // 300 / 10
#define ROWF 50           // floats per t-row (V*M)
#define CSLAB 15000       // floats per channel slab (T*ROWF)
#define SM_CH 600         // input floats per channel in smem
#define SLABF (RPT * ROWF)   // 500 floats per output slab segment
#define SLABB (SLABF * 4)    // 2000 bytes per bulk copy

__device__ __forceinline__ uint32_t smem_u32(const void* p)
{
    uint32_t a;
    asm("{ .reg .u64 t; cvta.to.shared.u64 t, %1; cvt.u32.u64 %0, t; }"
        : "=r"(a) : "l"(p));
    return a;
}

__global__ __launch_bounds__(256, 5) void egcn_preprocess_v12(
    const float* __restrict__ x,
    const int* __restrict__ conn,
    float* __restrict__ out)
{
    __shared__ float si[C_ * SM_CH];                      // 7.2 KB input tile
    __shared__ __align__(16) float so[18 * SLABF];        // 36 KB output tile

    const int tid  = threadIdx.x;
    const int n    = blockIdx.x / TILES_PER_N;
    const int tile = blockIdx.x % TILES_PER_N;
    const int t0   = tile * RPT;

    const float* xn = x + n * (C_ * CSLAB);

    // ---- stage input tile ----
    if (t0 + TILE_ROWS <= T_) {
        #pragma unroll
        for (int k = 0; k < 2; ++k) {
            int idx = tid + k * 256;
            if (idx < 450) {                              // 3ch x 150 float4
                int c   = idx / 150;
                int rem = idx - c * 150;
                const float4* src = (const float4*)(xn + c * CSLAB + t0 * ROWF);
                ((float4*)(si + c * SM_CH))[rem] = src[rem];
            }
        }
    } else {
        // last tile (t0 = 290): per-float2 row clamp
        for (int idx = tid; idx < C_ * TILE_ROWS * V_; idx += 256) {
            int c   = idx / (TILE_ROWS * V_);
            int rem = idx - c * (TILE_ROWS * V_);
            int r   = rem / V_;
            int v   = rem - r * V_;
            int gt  = t0 + r; if (gt > T_ - 1) gt = T_ - 1;
            ((float2*)(si + c * SM_CH + r * ROWF))[v] =
                ((const float2*)(xn + c * CSLAB + gt * ROWF))[v];
        }
    }
    __syncthreads();

    // ---- compute into smem output tile ----
    if (tid < RPT * V_) {
        const int r = tid / V_;                           // 0..9
        const int v = tid - r * V_;                       // 0..24
        const int t = t0 + r;
        const int pv = conn[v];
        const float sel = (t < T_ - 2) ? 1.0f : 0.0f;

        const int oo = r * ROWF + 2 * v;                  // offset within a slab

        float2 a[3], bv[3];
#pragma unroll
        for (int c = 0; c < C_; ++c) {
            const float* base = si + c * SM_CH + r * ROWF;
            float2 av  = ((const float2*)base)[v];
            float2 cen = ((const float2*)base)[1];
            float2 par = ((const float2*)base)[pv];
            float2 n1  = ((const float2*)(base + ROWF))[v];
            float2 n2  = ((const float2*)(base + 2 * ROWF))[v];

            a[c]  = av;
            bv[c] = make_float2(av.x - par.x, av.y - par.y);

            *(float2*)(so + (c     ) * SLABF + oo) = av;                          // joint: x
            *(float2*)(so + (c + 3 ) * SLABF + oo) =
                make_float2(av.x - cen.x, av.y - cen.y);                          // x - center
            *(float2*)(so + (c + 6 ) * SLABF + oo) =
                make_float2((n1.x - av.x) * sel, (n1.y - av.y) * sel);            // v1
            *(float2*)(so + (c + 9 ) * SLABF + oo) =
                make_float2((n2.x - av.x) * sel, (n2.y - av.y) * sel);            // v2
            *(float2*)(so + (c + 12) * SLABF + oo) = bv[c];                       // bone vec
        }

        float sx = bv[0].x * bv[0].x + bv[1].x * bv[1].x + bv[2].x * bv[2].x;
        float sy = bv[0].y * bv[0].y + bv[1].y * bv[1].y + bv[2].y * bv[2].y;
        float rlx = 1.0f / (sqrtf(sx) + 1e-4f);
        float rly = 1.0f / (sqrtf(sy) + 1e-4f);

#pragma unroll
        for (int c = 0; c < C_; ++c) {
            *(float2*)(so + (c + 15) * SLABF + oo) =
                make_float2(acosf(bv[c].x * rlx), acosf(bv[c].y * rly));          // bone angle
        }
    }
    __syncthreads();

    // ---- TMA bulk stores: 18 slabs x 2000B, one issuing thread ----
    if (tid == 0) {
        asm volatile("fence.proxy.async.shared::cta;" ::: "memory");
        float* og = out + (size_t)n * 18 * CSLAB + t0 * ROWF;
        uint32_t sbase = smem_u32(so);
#pragma unroll
        for (int j = 0; j < 18; ++j) {
            asm volatile(
                "cp.async.bulk.global.shared::cta.bulk_group [%0], [%1], %2;"
                :: "l"(og + (size_t)j * CSLAB),
                   "r"(sbase + j * SLABB),
                   "n"(SLABB)
                : "memory");
        }
        asm volatile("cp.async.bulk.commit_group;" ::: "memory");
        asm volatile("cp.async.bulk.wait_group 0;" ::: "memory");
    }
}

extern "C" void kernel_launch(void* const* d_in, const int* in_sizes, int n_in,
                              void* d_out, int out_size)
{
    const float* x  = (const float*)d_in[0];
    const int* conn = (const int*)d_in[1];
    float* out      = (float*)d_out;

    const int blocks = N_ * TILES_PER_N;     // 3840
    egcn_preprocess_v12<<<blocks, 256>>>(x, conn, out);
}